// round 7
// baseline (speedup 1.0000x reference)
#include <cuda_runtime.h>
#include <cstdint>

#define DIM 496
#define ROW_BYTES (DIM * 4)   // 1984 B, multiple of 16
#define NSLOT 4               // pipeline slots == tiles per block

// pair index of (x,y), x<y, in itertools.combinations(range(32),2) order
__device__ __forceinline__ int pidx(int x, int y) {
    return x * 31 - ((x * (x - 1)) >> 1) + (y - x - 1);
}

// Decode orbit o in [0,124): member basis indices m[0..3] as m[alpha*2+beta];
// outer gate gO acts on alpha (pairs (0,2),(1,3)), inner gI on beta ((0,1),(2,3)).
// Gate 15 == identity.
__device__ __forceinline__ void decode_orbit(int o, int m[4], int& gO, int& gI) {
    if (o < 105) {                       // cross-block (g<h<15): R_g (x) R_h
        int g = 0, rem = o;
        while (rem >= 14 - g) { rem -= 14 - g; ++g; }
        int h = g + 1 + rem;
        gO = g; gI = h;
        m[0] = pidx(2 * g,     2 * h);
        m[1] = pidx(2 * g,     2 * h + 1);
        m[2] = pidx(2 * g + 1, 2 * h);
        m[3] = pidx(2 * g + 1, 2 * h + 1);
    } else if (o < 120) {                // block g with qubits 30/31: R_g (x) I
        int g = o - 105;
        gO = g; gI = 15;
        m[0] = pidx(2 * g,     30);
        m[1] = pidx(2 * g,     31);
        m[2] = pidx(2 * g + 1, 30);
        m[3] = pidx(2 * g + 1, 31);
    } else {                             // 16 identity singletons, 4 per orbit
        int j = o - 120;
        gO = 15; gI = 15;
#pragma unroll
        for (int k = 0; k < 4; ++k) {
            int q = 4 * j + k;
            m[k] = pidx(2 * q, 2 * q + 1);
        }
    }
}

__device__ __forceinline__ uint32_t smem_u32(const void* p) {
    return (uint32_t)__cvta_generic_to_shared(p);
}

// Grid 248 x 128 threads. Block B owns row-orbit (4*B)>>3 and batches
// (4*B)&7 .. +3 — i.e. ONE row orbit, 4 batches = 4 tiles of 4x496 floats.
// All 4 tile loads issued up front via bulk-async against 4 mbarriers;
// compute streams through slots in order; stores via bulk_group.
__global__ __launch_bounds__(128) void rbs_density_kernel(
    const float* __restrict__ rho, const float* __restrict__ angles,
    float* __restrict__ out)
{
    __shared__ __align__(16) float S[NSLOT][4][DIM];   // 31.75 KB
    __shared__ __align__(8) uint64_t mbar[NSLOT];
    __shared__ float cs[16], sn[16];

    const int t    = threadIdx.x;
    const int base = blockIdx.x * 4;       // first tile id
    const int ro   = base >> 3;            // same row-orbit for all 4 tiles
    const int b0   = base & 7;             // first batch (0 or 4)

    int rm[4], rgO, rgI;
    decode_orbit(ro, rm, rgO, rgI);

    // ---- Prologue: thread 0 inits 4 mbarriers and fires all 16 bulk loads.
    if (t == 0) {
#pragma unroll
        for (int s = 0; s < NSLOT; ++s)
            asm volatile("mbarrier.init.shared.b64 [%0], 1;"
                         :: "r"(smem_u32(&mbar[s])) : "memory");
        asm volatile("fence.proxy.async.shared::cta;" ::: "memory");
#pragma unroll
        for (int s = 0; s < NSLOT; ++s) {
            const uint32_t mb = smem_u32(&mbar[s]);
            asm volatile("mbarrier.arrive.expect_tx.shared.b64 _, [%0], %1;"
                         :: "r"(mb), "r"(4 * ROW_BYTES) : "memory");
            const float* bp = rho + (size_t)(b0 + s) * DIM * DIM;
#pragma unroll
            for (int i = 0; i < 4; ++i) {
                asm volatile(
                    "cp.async.bulk.shared::cluster.global.mbarrier::complete_tx::bytes "
                    "[%0], [%1], %2, [%3];"
                    :: "r"(smem_u32(S[s][i])), "l"(bp + (size_t)rm[i] * DIM),
                       "r"(ROW_BYTES), "r"(mb)
                    : "memory");
            }
        }
    }

    // ---- Angle table (overlaps with loads in flight).
    if (t < 16) {
        if (t < 15) { float s, c; sincosf(angles[t], &s, &c); cs[t] = c; sn[t] = s; }
        else        { cs[15] = 1.0f; sn[15] = 0.0f; }
    }
    __syncthreads();                       // table ready + mbar init visible

    const float rci = cs[rgI], rsi = sn[rgI];
    const float rco = cs[rgO], rso = sn[rgO];

    int cm[4];
    float cci = 1.f, csi = 0.f, cco = 1.f, cso = 0.f;
    if (t < 124) {
        int cgO, cgI;
        decode_orbit(t, cm, cgO, cgI);
        cci = cs[cgI]; csi = sn[cgI];
        cco = cs[cgO]; cso = sn[cgO];
    }

    // ---- Stream the 4 slots in arrival order.
#pragma unroll
    for (int s = 0; s < NSLOT; ++s) {
        // Wait slot full (phase 0), acquire.
        {
            const uint32_t mb = smem_u32(&mbar[s]);
            uint32_t done;
            asm volatile(
                "{\n\t.reg .pred p;\n\t"
                "mbarrier.try_wait.parity.acquire.cta.shared::cta.b64 p, [%1], 0;\n\t"
                "selp.b32 %0, 1, 0, p;\n\t}"
                : "=r"(done) : "r"(mb) : "memory");
            while (!done) {
                asm volatile(
                    "{\n\t.reg .pred p;\n\t"
                    "mbarrier.try_wait.parity.acquire.cta.shared::cta.b64 p, [%1], 0, 0x989680;\n\t"
                    "selp.b32 %0, 1, 0, p;\n\t}"
                    : "=r"(done) : "r"(mb) : "memory");
            }
        }

        // Row transform (in place; each thread a strided set of columns).
        for (int c = t; c < DIM; c += 128) {
            float v0 = S[s][0][c], v1 = S[s][1][c];
            float v2 = S[s][2][c], v3 = S[s][3][c];
            float t0 = rci * v0 + rsi * v1, t1 = rci * v1 - rsi * v0;
            float t2 = rci * v2 + rsi * v3, t3 = rci * v3 - rsi * v2;
            S[s][0][c] = rco * t0 + rso * t2;  S[s][2][c] = rco * t2 - rso * t0;
            S[s][1][c] = rco * t1 + rso * t3;  S[s][3][c] = rco * t3 - rso * t1;
        }
        __syncthreads();

        // Column transform (thread t owns col-orbit t; disjoint 4-col sets).
        if (t < 124) {
#pragma unroll
            for (int i = 0; i < 4; ++i) {
                float w0 = S[s][i][cm[0]], w1 = S[s][i][cm[1]];
                float w2 = S[s][i][cm[2]], w3 = S[s][i][cm[3]];
                float t0 = cci * w0 + csi * w1, t1 = cci * w1 - csi * w0;
                float t2 = cci * w2 + csi * w3, t3 = cci * w3 - csi * w2;
                S[s][i][cm[0]] = cco * t0 + cso * t2;
                S[s][i][cm[2]] = cco * t2 - cso * t0;
                S[s][i][cm[1]] = cco * t1 + cso * t3;
                S[s][i][cm[3]] = cco * t3 - cso * t1;
            }
        }
        __syncthreads();

        // Bulk store this tile; completion drained once at kernel end.
        if (t == 0) {
            asm volatile("fence.proxy.async.shared::cta;" ::: "memory");
            float* op = out + (size_t)(b0 + s) * DIM * DIM;
#pragma unroll
            for (int i = 0; i < 4; ++i) {
                asm volatile(
                    "cp.async.bulk.global.shared::cta.bulk_group [%0], [%1], %2;"
                    :: "l"(op + (size_t)rm[i] * DIM), "r"(smem_u32(S[s][i])),
                       "r"(ROW_BYTES)
                    : "memory");
            }
            asm volatile("cp.async.bulk.commit_group;" ::: "memory");
        }
    }

    if (t == 0)
        asm volatile("cp.async.bulk.wait_group 0;" ::: "memory");
}

extern "C" void kernel_launch(void* const* d_in, const int* in_sizes, int n_in,
                              void* d_out, int out_size) {
    const float* rho = (const float*)d_in[0];
    const float* ang = (const float*)d_in[1];
    if (n_in >= 2 && in_sizes[0] == 15) {   // defensive input-order swap
        rho = (const float*)d_in[1];
        ang = (const float*)d_in[0];
    }
    rbs_density_kernel<<<248, 128>>>(rho, ang, (float*)d_out);
}

// round 9
// speedup vs baseline: 1.1791x; 1.1791x over previous
#include <cuda_runtime.h>

#define DIM 496

// pair index of (x,y), x<y, in itertools.combinations(range(32),2) order
__device__ __forceinline__ int pidx(int x, int y) {
    return x * 31 - ((x * (x - 1)) >> 1) + (y - x - 1);
}

// Decode orbit o in [0,124): member basis indices m[0..3] as m[alpha*2+beta];
// outer gate gO acts on alpha (pairs (0,2),(1,3)), inner gI on beta ((0,1),(2,3)).
// Gate 15 == identity.
__device__ __forceinline__ void decode_orbit(int o, int m[4], int& gO, int& gI) {
    if (o < 105) {                       // cross-block (g<h<15): R_g (x) R_h
        int g = 0, rem = o;
        while (rem >= 14 - g) { rem -= 14 - g; ++g; }
        int h = g + 1 + rem;
        gO = g; gI = h;
        m[0] = pidx(2 * g,     2 * h);
        m[1] = pidx(2 * g,     2 * h + 1);
        m[2] = pidx(2 * g + 1, 2 * h);
        m[3] = pidx(2 * g + 1, 2 * h + 1);
    } else if (o < 120) {                // block g with qubits 30/31: R_g (x) I
        int g = o - 105;
        gO = g; gI = 15;
        m[0] = pidx(2 * g,     30);
        m[1] = pidx(2 * g,     31);
        m[2] = pidx(2 * g + 1, 30);
        m[3] = pidx(2 * g + 1, 31);
    } else {                             // 16 identity singletons, 4 per orbit
        int j = o - 120;
        gO = 15; gI = 15;
#pragma unroll
        for (int k = 0; k < 4; ++k) {
            int q = 4 * j + k;
            m[k] = pidx(2 * q, 2 * q + 1);
        }
    }
}

__device__ __forceinline__ void gate_cs(const float* __restrict__ angles,
                                        int g, float& c, float& s) {
    if (g < 15) sincosf(__ldg(angles + g), &s, &c);
    else { c = 1.0f; s = 0.0f; }
}

// Block = (row-orbit ro, batch b), 128 threads, thread t = float4 chunk
// (active t<124) and col-orbit t in phase 2. Row rotation fused into the
// load in registers; one smem round-trip for the column rotation; 2 barriers.
__global__ __launch_bounds__(128) void rbs_density_kernel(
    const float* __restrict__ rho, const float* __restrict__ angles,
    float* __restrict__ out)
{
    __shared__ __align__(16) float S[4][DIM];   // 7936 B

    const int t  = threadIdx.x;
    const int ro = blockIdx.x;
    const int b  = blockIdx.y;

    int rm[4], rgO, rgI;
    decode_orbit(ro, rm, rgO, rgI);

    const size_t boff = (size_t)b * DIM * DIM;

    if (t < 124) {
        // 4 independent LDG.128, issued before the trig computes below use them.
        float4 v0 = ((const float4*)(rho + boff + (size_t)rm[0] * DIM))[t];
        float4 v1 = ((const float4*)(rho + boff + (size_t)rm[1] * DIM))[t];
        float4 v2 = ((const float4*)(rho + boff + (size_t)rm[2] * DIM))[t];
        float4 v3 = ((const float4*)(rho + boff + (size_t)rm[3] * DIM))[t];

        // Row-gate trig (block-uniform), overlapped with loads in flight.
        float ci, si, co, so;
        gate_cs(angles, rgI, ci, si);
        gate_cs(angles, rgO, co, so);

        // Row transform in registers: inner on (0,1),(2,3); outer on (0,2),(1,3).
        float4 w0, w1, w2, w3;
        {
            float t0, t1, t2, t3;
            t0 = ci * v0.x + si * v1.x;  t1 = ci * v1.x - si * v0.x;
            t2 = ci * v2.x + si * v3.x;  t3 = ci * v3.x - si * v2.x;
            w0.x = co * t0 + so * t2;  w2.x = co * t2 - so * t0;
            w1.x = co * t1 + so * t3;  w3.x = co * t3 - so * t1;

            t0 = ci * v0.y + si * v1.y;  t1 = ci * v1.y - si * v0.y;
            t2 = ci * v2.y + si * v3.y;  t3 = ci * v3.y - si * v2.y;
            w0.y = co * t0 + so * t2;  w2.y = co * t2 - so * t0;
            w1.y = co * t1 + so * t3;  w3.y = co * t3 - so * t1;

            t0 = ci * v0.z + si * v1.z;  t1 = ci * v1.z - si * v0.z;
            t2 = ci * v2.z + si * v3.z;  t3 = ci * v3.z - si * v2.z;
            w0.z = co * t0 + so * t2;  w2.z = co * t2 - so * t0;
            w1.z = co * t1 + so * t3;  w3.z = co * t3 - so * t1;

            t0 = ci * v0.w + si * v1.w;  t1 = ci * v1.w - si * v0.w;
            t2 = ci * v2.w + si * v3.w;  t3 = ci * v3.w - si * v2.w;
            w0.w = co * t0 + so * t2;  w2.w = co * t2 - so * t0;
            w1.w = co * t1 + so * t3;  w3.w = co * t3 - so * t1;
        }

        *(float4*)&S[0][4 * t] = w0;
        *(float4*)&S[1][4 * t] = w1;
        *(float4*)&S[2][4 * t] = w2;
        *(float4*)&S[3][4 * t] = w3;
    }
    __syncthreads();

    // Column transform: thread t owns col-orbit t (disjoint 4-column sets ->
    // in-place safe), applied to all 4 rows.
    if (t < 124) {
        int cm[4], cgO, cgI;
        decode_orbit(t, cm, cgO, cgI);
        float ci, si, co, so;
        gate_cs(angles, cgI, ci, si);
        gate_cs(angles, cgO, co, so);
#pragma unroll
        for (int i = 0; i < 4; ++i) {
            float u0 = S[i][cm[0]], u1 = S[i][cm[1]];
            float u2 = S[i][cm[2]], u3 = S[i][cm[3]];
            float t0 = ci * u0 + si * u1, t1 = ci * u1 - si * u0;
            float t2 = ci * u2 + si * u3, t3 = ci * u3 - si * u2;
            S[i][cm[0]] = co * t0 + so * t2;  S[i][cm[2]] = co * t2 - so * t0;
            S[i][cm[1]] = co * t1 + so * t3;  S[i][cm[3]] = co * t3 - so * t1;
        }
    }
    __syncthreads();

    // Streaming float4 stores (output is write-once per replay).
    if (t < 124) {
#pragma unroll
        for (int i = 0; i < 4; ++i)
            __stcs((float4*)(out + boff + (size_t)rm[i] * DIM) + t,
                   *(const float4*)&S[i][4 * t]);
    }
}

extern "C" void kernel_launch(void* const* d_in, const int* in_sizes, int n_in,
                              void* d_out, int out_size) {
    const float* rho = (const float*)d_in[0];
    const float* ang = (const float*)d_in[1];
    if (n_in >= 2 && in_sizes[0] == 15) {   // defensive input-order swap
        rho = (const float*)d_in[1];
        ang = (const float*)d_in[0];
    }
    dim3 grid(124, 8);
    rbs_density_kernel<<<grid, 128>>>(rho, ang, (float*)d_out);
}

// round 10
// speedup vs baseline: 1.1835x; 1.0037x over previous
#include <cuda_runtime.h>

#define DIM 496

// pair index of (x,y), x<y, in itertools.combinations(range(32),2) order
__device__ __forceinline__ int pidx(int x, int y) {
    return x * 31 - ((x * (x - 1)) >> 1) + (y - x - 1);
}

// Decode orbit o in [0,124): member basis indices m[0..3] as m[alpha*2+beta];
// outer gate gO acts on alpha (pairs (0,2),(1,3)), inner gI on beta ((0,1),(2,3)).
// Gate 15 == identity.
__device__ __forceinline__ void decode_orbit(int o, int m[4], int& gO, int& gI) {
    if (o < 105) {                       // cross-block (g<h<15): R_g (x) R_h
        int g = 0, rem = o;
        while (rem >= 14 - g) { rem -= 14 - g; ++g; }
        int h = g + 1 + rem;
        gO = g; gI = h;
        m[0] = pidx(2 * g,     2 * h);
        m[1] = pidx(2 * g,     2 * h + 1);
        m[2] = pidx(2 * g + 1, 2 * h);
        m[3] = pidx(2 * g + 1, 2 * h + 1);
    } else if (o < 120) {                // block g with qubits 30/31: R_g (x) I
        int g = o - 105;
        gO = g; gI = 15;
        m[0] = pidx(2 * g,     30);
        m[1] = pidx(2 * g,     31);
        m[2] = pidx(2 * g + 1, 30);
        m[3] = pidx(2 * g + 1, 31);
    } else {                             // 16 identity singletons, 4 per orbit
        int j = o - 120;
        gO = 15; gI = 15;
#pragma unroll
        for (int k = 0; k < 4; ++k) {
            int q = 4 * j + k;
            m[k] = pidx(2 * q, 2 * q + 1);
        }
    }
}

__device__ __forceinline__ void gate_cs(const float* __restrict__ angles,
                                        int g, float& c, float& s) {
    if (g < 15) sincosf(__ldg(angles + g), &s, &c);
    else { c = 1.0f; s = 0.0f; }
}

// Block = (row-orbit ro, batch b), 128 threads, thread t = float4 chunk
// (active t<124) and col-orbit t in phase 2. Row rotation fused into the
// load in registers; one smem round-trip for the column rotation; 2 barriers.
__global__ __launch_bounds__(128) void rbs_density_kernel(
    const float* __restrict__ rho, const float* __restrict__ angles,
    float* __restrict__ out)
{
    __shared__ __align__(16) float S[4][DIM];   // 7936 B

    const int t  = threadIdx.x;
    const int ro = blockIdx.x;
    const int b  = blockIdx.y;

    int rm[4], rgO, rgI;
    decode_orbit(ro, rm, rgO, rgI);

    const size_t boff = (size_t)b * DIM * DIM;

    if (t < 124) {
        // 4 independent LDG.128, issued before the trig computes below use them.
        float4 v0 = ((const float4*)(rho + boff + (size_t)rm[0] * DIM))[t];
        float4 v1 = ((const float4*)(rho + boff + (size_t)rm[1] * DIM))[t];
        float4 v2 = ((const float4*)(rho + boff + (size_t)rm[2] * DIM))[t];
        float4 v3 = ((const float4*)(rho + boff + (size_t)rm[3] * DIM))[t];

        // Row-gate trig (block-uniform), overlapped with loads in flight.
        float ci, si, co, so;
        gate_cs(angles, rgI, ci, si);
        gate_cs(angles, rgO, co, so);

        // Row transform in registers: inner on (0,1),(2,3); outer on (0,2),(1,3).
        float4 w0, w1, w2, w3;
        {
            float t0, t1, t2, t3;
            t0 = ci * v0.x + si * v1.x;  t1 = ci * v1.x - si * v0.x;
            t2 = ci * v2.x + si * v3.x;  t3 = ci * v3.x - si * v2.x;
            w0.x = co * t0 + so * t2;  w2.x = co * t2 - so * t0;
            w1.x = co * t1 + so * t3;  w3.x = co * t3 - so * t1;

            t0 = ci * v0.y + si * v1.y;  t1 = ci * v1.y - si * v0.y;
            t2 = ci * v2.y + si * v3.y;  t3 = ci * v3.y - si * v2.y;
            w0.y = co * t0 + so * t2;  w2.y = co * t2 - so * t0;
            w1.y = co * t1 + so * t3;  w3.y = co * t3 - so * t1;

            t0 = ci * v0.z + si * v1.z;  t1 = ci * v1.z - si * v0.z;
            t2 = ci * v2.z + si * v3.z;  t3 = ci * v3.z - si * v2.z;
            w0.z = co * t0 + so * t2;  w2.z = co * t2 - so * t0;
            w1.z = co * t1 + so * t3;  w3.z = co * t3 - so * t1;

            t0 = ci * v0.w + si * v1.w;  t1 = ci * v1.w - si * v0.w;
            t2 = ci * v2.w + si * v3.w;  t3 = ci * v3.w - si * v2.w;
            w0.w = co * t0 + so * t2;  w2.w = co * t2 - so * t0;
            w1.w = co * t1 + so * t3;  w3.w = co * t3 - so * t1;
        }

        *(float4*)&S[0][4 * t] = w0;
        *(float4*)&S[1][4 * t] = w1;
        *(float4*)&S[2][4 * t] = w2;
        *(float4*)&S[3][4 * t] = w3;
    }
    __syncthreads();

    // Column transform: thread t owns col-orbit t (disjoint 4-column sets ->
    // in-place safe), applied to all 4 rows.
    if (t < 124) {
        int cm[4], cgO, cgI;
        decode_orbit(t, cm, cgO, cgI);
        float ci, si, co, so;
        gate_cs(angles, cgI, ci, si);
        gate_cs(angles, cgO, co, so);
#pragma unroll
        for (int i = 0; i < 4; ++i) {
            float u0 = S[i][cm[0]], u1 = S[i][cm[1]];
            float u2 = S[i][cm[2]], u3 = S[i][cm[3]];
            float t0 = ci * u0 + si * u1, t1 = ci * u1 - si * u0;
            float t2 = ci * u2 + si * u3, t3 = ci * u3 - si * u2;
            S[i][cm[0]] = co * t0 + so * t2;  S[i][cm[2]] = co * t2 - so * t0;
            S[i][cm[1]] = co * t1 + so * t3;  S[i][cm[3]] = co * t3 - so * t1;
        }
    }
    __syncthreads();

    // Plain coalesced float4 stores (no eviction hints).
    if (t < 124) {
#pragma unroll
        for (int i = 0; i < 4; ++i)
            ((float4*)(out + boff + (size_t)rm[i] * DIM))[t] =
                *(const float4*)&S[i][4 * t];
    }
}

extern "C" void kernel_launch(void* const* d_in, const int* in_sizes, int n_in,
                              void* d_out, int out_size) {
    const float* rho = (const float*)d_in[0];
    const float* ang = (const float*)d_in[1];
    if (n_in >= 2 && in_sizes[0] == 15) {   // defensive input-order swap
        rho = (const float*)d_in[1];
        ang = (const float*)d_in[0];
    }
    dim3 grid(124, 8);
    rbs_density_kernel<<<grid, 128>>>(rho, ang, (float*)d_out);
}

// round 11
// speedup vs baseline: 1.2344x; 1.0430x over previous
#include <cuda_runtime.h>

#define DIM 496

// pair index of (x,y), x<y, in itertools.combinations(range(32),2) order
__device__ __forceinline__ int pidx(int x, int y) {
    return x * 31 - ((x * (x - 1)) >> 1) + (y - x - 1);
}

// Decode orbit o in [0,124): 4 member basis indices m[0..3] laid out as
// m[alpha*2+beta], outer gate gO acting on alpha, inner gate gI on beta.
// Gate id 15 == identity (cos=1, sin=0).
__device__ __forceinline__ void decode_orbit(int o, int m[4], int& gO, int& gI) {
    if (o < 105) {                       // cross-block (g<h<15): R_g (x) R_h
        int g = 0, rem = o;
        while (rem >= 14 - g) { rem -= 14 - g; ++g; }
        int h = g + 1 + rem;
        gO = g; gI = h;
        m[0] = pidx(2 * g,     2 * h);
        m[1] = pidx(2 * g,     2 * h + 1);
        m[2] = pidx(2 * g + 1, 2 * h);
        m[3] = pidx(2 * g + 1, 2 * h + 1);
    } else if (o < 120) {                // block g paired with qubits 30/31: R_g (x) I
        int g = o - 105;
        gO = g; gI = 15;
        m[0] = pidx(2 * g,     30);
        m[1] = pidx(2 * g,     31);
        m[2] = pidx(2 * g + 1, 30);
        m[3] = pidx(2 * g + 1, 31);
    } else {                             // 16 identity singletons grouped 4-at-a-time
        int j = o - 120;
        gO = 15; gI = 15;
#pragma unroll
        for (int k = 0; k < 4; ++k) {
            int q = 4 * j + k;
            m[k] = pidx(2 * q, 2 * q + 1);
        }
    }
}

__global__ __launch_bounds__(128) void rbs_density_kernel(
    const float* __restrict__ rho, const float* __restrict__ angles,
    float* __restrict__ out)
{
    __shared__ float S[4][DIM];          // 4 rows of one row-orbit, 7936 B
    __shared__ float cs[16], sn[16];

    const int tid = threadIdx.x;
    const int ro  = blockIdx.x;          // row orbit 0..123
    const int b   = blockIdx.y;          // batch 0..7

    if (tid < 16) {
        if (tid < 15) {
            float s, c;
            sincosf(angles[tid], &s, &c);
            cs[tid] = c; sn[tid] = s;
        } else {
            cs[15] = 1.0f; sn[15] = 0.0f;
        }
    }

    int rm[4], rgO, rgI;
    decode_orbit(ro, rm, rgO, rgI);

    const size_t boff = (size_t)b * DIM * DIM;

    // coalesced float4 load of the 4 rows (496 floats = 124 float4 each)
    if (tid < 124) {
#pragma unroll
        for (int i = 0; i < 4; ++i) {
            const float4 v = ((const float4*)(rho + boff + (size_t)rm[i] * DIM))[tid];
            ((float4*)S[i])[tid] = v;
        }
    }
    __syncthreads();

    // Row transform: M <- U_r * M. Each thread owns a strided set of columns.
    {
        const float ci = cs[rgI], si = sn[rgI];
        const float co = cs[rgO], so = sn[rgO];
        for (int c = tid; c < DIM; c += 128) {
            float v0 = S[0][c], v1 = S[1][c], v2 = S[2][c], v3 = S[3][c];
            // inner rotation R_h on beta: pairs (0,1) and (2,3)
            float t0 = ci * v0 + si * v1, t1 = ci * v1 - si * v0;
            float t2 = ci * v2 + si * v3, t3 = ci * v3 - si * v2;
            // outer rotation R_g on alpha: pairs (0,2) and (1,3)
            S[0][c] = co * t0 + so * t2;  S[2][c] = co * t2 - so * t0;
            S[1][c] = co * t1 + so * t3;  S[3][c] = co * t3 - so * t1;
        }
    }
    __syncthreads();

    // Column transform: M <- M * U_c^T. Thread t owns column-orbit t
    // (disjoint 4-column sets -> in-place safe).
    if (tid < 124) {
        int cm[4], cgO, cgI;
        decode_orbit(tid, cm, cgO, cgI);
        const float ci = cs[cgI], si = sn[cgI];
        const float co = cs[cgO], so = sn[cgO];
#pragma unroll
        for (int i = 0; i < 4; ++i) {
            float w0 = S[i][cm[0]], w1 = S[i][cm[1]];
            float w2 = S[i][cm[2]], w3 = S[i][cm[3]];
            float t0 = ci * w0 + si * w1, t1 = ci * w1 - si * w0;
            float t2 = ci * w2 + si * w3, t3 = ci * w3 - si * w2;
            S[i][cm[0]] = co * t0 + so * t2;  S[i][cm[2]] = co * t2 - so * t0;
            S[i][cm[1]] = co * t1 + so * t3;  S[i][cm[3]] = co * t3 - so * t1;
        }
    }
    __syncthreads();

    // coalesced float4 store of the 4 transformed rows
    if (tid < 124) {
#pragma unroll
        for (int i = 0; i < 4; ++i) {
            ((float4*)(out + boff + (size_t)rm[i] * DIM))[tid] =
                ((const float4*)S[i])[tid];
        }
    }
}

extern "C" void kernel_launch(void* const* d_in, const int* in_sizes, int n_in,
                              void* d_out, int out_size) {
    const float* rho = (const float*)d_in[0];
    const float* ang = (const float*)d_in[1];
    // defensive: metadata order should be (input_state, angles); swap if reversed
    if (n_in >= 2 && in_sizes[0] == 15) {
        rho = (const float*)d_in[1];
        ang = (const float*)d_in[0];
    }
    dim3 grid(124, 8);
    rbs_density_kernel<<<grid, 128>>>(rho, ang, (float*)d_out);
}